// round 10
// baseline (speedup 1.0000x reference)
#include <cuda_runtime.h>
#include <math.h>

// ---------------- scratch (device globals; no allocation) ----------------
__device__ float g_k1  [16 * 512 * 200];   // key conv1 out
__device__ float g_k   [16 *  80 * 200];   // key encoder out
__device__ float g_q1  [16 * 160 * 800];   // query conv1 out
__device__ float g_qf  [16 *  80 * 800];   // query encoder out
__device__ float g_kw1T[768 * 512];        // kw1 transposed [(ci*3+k)][co]
__device__ float g_qw1T[240 * 160];
__device__ float g_kw2T[512 *  80];        // kw2 transposed [ci][co]
__device__ float g_qw2T[160 *  80];
__device__ float g_qw3T[ 80 *  80];

// ---------------- packed fp32x2 FMA (Blackwell) ---------------------------
__device__ __forceinline__ float2 ffma2(float2 a, float2 b, float2 c) {
    unsigned long long ua = *reinterpret_cast<unsigned long long*>(&a);
    unsigned long long ub = *reinterpret_cast<unsigned long long*>(&b);
    unsigned long long uc = *reinterpret_cast<unsigned long long*>(&c);
    unsigned long long ud;
    asm("fma.rn.f32x2 %0, %1, %2, %3;" : "=l"(ud) : "l"(ua), "l"(ub), "l"(uc));
    return *reinterpret_cast<float2*>(&ud);
}
__device__ __forceinline__ float2 dup(float v) { return make_float2(v, v); }

// =================== PREP: transpose all weights ==========================
__global__ void prep_kernel(const float* __restrict__ kw1, const float* __restrict__ qw1,
                            const float* __restrict__ kw2, const float* __restrict__ qw2,
                            const float* __restrict__ qw3,
                            float* __restrict__ kw1T, float* __restrict__ qw1T,
                            float* __restrict__ kw2T, float* __restrict__ qw2T,
                            float* __restrict__ qw3T)
{
    int i = blockIdx.x * 256 + threadIdx.x;
    if (i < 393216) {                    // kw1: (512,256,3)
        int r = i >> 9, co = i & 511;
        int ci = r / 3, k = r - ci * 3;
        kw1T[i] = kw1[(co * 256 + ci) * 3 + k];
        return;
    }
    i -= 393216;
    if (i < 38400) {                     // qw1: (160,80,3)
        int r = i / 160, co = i - r * 160;
        int ci = r / 3, k = r - ci * 3;
        qw1T[i] = qw1[(co * 80 + ci) * 3 + k];
        return;
    }
    i -= 38400;
    if (i < 40960) {                     // kw2: (80,512,1)
        int ci = i / 80, co = i - ci * 80;
        kw2T[i] = kw2[co * 512 + ci];
        return;
    }
    i -= 40960;
    if (i < 12800) {                     // qw2: (80,160,1)
        int ci = i / 80, co = i - ci * 80;
        qw2T[i] = qw2[co * 160 + ci];
        return;
    }
    i -= 12800;
    if (i < 6400) {                      // qw3: (80,80,1)
        int ci = i / 80, co = i - ci * 80;
        qw3T[i] = qw3[co * 80 + ci];
    }
}

// =================== STAGE A: both k=3 pad=1 convs ========================
// x stored DUPLICATED in smem: sx row = 68 float2 (136 floats), value j at
// float offset 2j. Hot loop reads xv pairs via LDS.128 with zero MOVs.
// smem: sx[CICH][136] + sw[CICH*3][COT]
template<int CIN, int COUT, int TLEN, int CPAIRS, int CICH>
__device__ __forceinline__ void conv3_body(
    const float* __restrict__ x, const float* __restrict__ wT,
    const float* __restrict__ bias, float* __restrict__ y,
    int b, int t_tile, int co_tile, float* smem)
{
    constexpr int COT = 32 * CPAIRS;
    constexpr int NW4 = CICH * 3 * COT / 4;
    float* sx = smem;                    // CICH * 136 (dup'd)
    float* sw = smem + CICH * 136;       // CICH*3*COT

    const int tid = threadIdx.x;
    const int cg = tid & 15, tg = tid >> 4;
    const int tt = tg * 4, ct = cg * 2 * CPAIRS;
    const int t0 = t_tile * 64, co0 = co_tile * COT;
    const bool active = (t0 + tt) < TLEN;

    float2 acc[CPAIRS][4] = {};

    for (int ci0 = 0; ci0 < CIN; ci0 += CICH) {
        __syncthreads();
        for (int idx = tid; idx < CICH * 66; idx += 256) {
            int cc = idx / 66, j = idx - cc * 66;
            int t = t0 + j - 1;
            float v = (t >= 0 && t < TLEN)
                ? x[((size_t)(b * CIN) + ci0 + cc) * TLEN + t] : 0.f;
            ((float2*)sx)[cc * 68 + j] = make_float2(v, v);
        }
        for (int idx = tid; idx < NW4; idx += 256) {
            int r = idx / (COT / 4), c4 = idx - r * (COT / 4);
            ((float4*)sw)[idx] =
                *(const float4*)&wT[(size_t)(ci0 * 3 + r) * COUT + co0 + c4 * 4];
        }
        __syncthreads();
        if (active) {
            #pragma unroll
            for (int cc = 0; cc < CICH; cc++) {
                const float* xr = &sx[cc * 136 + 2 * tt];
                float4 xd0 = *(const float4*)(xr);
                float4 xd1 = *(const float4*)(xr + 4);
                float4 xd2 = *(const float4*)(xr + 8);
                float2 xv[6] = { {xd0.x,xd0.y},{xd0.z,xd0.w},
                                 {xd1.x,xd1.y},{xd1.z,xd1.w},
                                 {xd2.x,xd2.y},{xd2.z,xd2.w} };
                float2 wk[3][CPAIRS];
                #pragma unroll
                for (int k = 0; k < 3; k++) {
                    const float* wb = &sw[(cc * 3 + k) * COT + ct];
                    if constexpr ((CPAIRS & 1) == 0) {
                        #pragma unroll
                        for (int q = 0; q < CPAIRS / 2; q++) {
                            float4 wv = *(const float4*)(wb + 4 * q);
                            wk[k][2*q]   = make_float2(wv.x, wv.y);
                            wk[k][2*q+1] = make_float2(wv.z, wv.w);
                        }
                    } else {
                        #pragma unroll
                        for (int p = 0; p < CPAIRS; p++)
                            wk[k][p] = *(const float2*)(wb + 2 * p);
                    }
                }
                #pragma unroll
                for (int u = 0; u < 4; u++)
                    #pragma unroll
                    for (int p = 0; p < CPAIRS; p++)
                        acc[p][u] = ffma2(wk[0][p], xv[u],
                                    ffma2(wk[1][p], xv[u+1],
                                    ffma2(wk[2][p], xv[u+2], acc[p][u])));
            }
        }
    }

    if (active) {
        #pragma unroll
        for (int p = 0; p < CPAIRS; p++) {
            int co = co0 + ct + 2 * p;
            float2 bv = *(const float2*)&bias[co];
            float4 v0 = { fmaxf(acc[p][0].x + bv.x, 0.f), fmaxf(acc[p][1].x + bv.x, 0.f),
                          fmaxf(acc[p][2].x + bv.x, 0.f), fmaxf(acc[p][3].x + bv.x, 0.f) };
            float4 v1 = { fmaxf(acc[p][0].y + bv.y, 0.f), fmaxf(acc[p][1].y + bv.y, 0.f),
                          fmaxf(acc[p][2].y + bv.y, 0.f), fmaxf(acc[p][3].y + bv.y, 0.f) };
            *(float4*)&y[((size_t)(b * COUT) + co    ) * TLEN + t0 + tt] = v0;
            *(float4*)&y[((size_t)(b * COUT) + co + 1) * TLEN + t0 + tt] = v1;
        }
    }
}

__global__ void __launch_bounds__(256)
stageA_kernel(
    const float* __restrict__ keys, const float* __restrict__ kb1,
    const float* __restrict__ queries, const float* __restrict__ qb1,
    float* __restrict__ k1out, float* __restrict__ q1out)
{
    extern __shared__ float smem[];
    int id = blockIdx.x;
    if (id < 512) {
        int b = id >> 5, r = id & 31;
        conv3_body<256, 512, 200, 2, 16>(keys, g_kw1T, kb1, k1out,
                                         b, r & 3, r >> 2, smem);
    } else {
        int j = id - 512;
        conv3_body<80, 160, 800, 5, 16>(queries, g_qw1T, qb1, q1out,
                                        j / 13, j % 13, 0, smem);
    }
}

// =================== STAGE B: key 1x1 (t-split) + query 1x1 chain =========
// phase-2 helper (sh2 non-dup, stride 128) — unchanged from R9
__device__ __forceinline__ void fma1x1_chunk(
    const float* __restrict__ sx, const float* __restrict__ sw,
    int tt, int cb, int CC, float2 acc[5][4])
{
    #pragma unroll 8
    for (int cc = 0; cc < CC; cc++) {
        float4 xq = *(const float4*)&sx[cc * 128 + tt];
        float2 xv[4] = { dup(xq.x), dup(xq.y), dup(xq.z), dup(xq.w) };
        const float2* wp = (const float2*)&sw[cc * 80 + cb];
        #pragma unroll
        for (int p = 0; p < 5; p++) {
            float2 wd = wp[p];
            #pragma unroll
            for (int u = 0; u < 4; u++)
                acc[p][u] = ffma2(wd, xv[u], acc[p][u]);
        }
    }
}

// key 1x1: t-tile 64; sx dup'd (row = 64 float2 = 128 floats)
__device__ __forceinline__ void key1x1_body(
    const float* __restrict__ x, const float* __restrict__ wT,
    const float* __restrict__ bias, float* __restrict__ y,
    int b, int t_tile, float* smem)
{
    float* sx = smem;          // 4096 floats (32 x 64 dup'd)
    float* sw = smem + 4096;   // 2560
    const int tid = threadIdx.x;
    const int cg = tid & 7, tg = tid >> 3;
    const int tt = tg * 2, cb = cg * 10;
    const int t0 = t_tile * 64;
    const bool active = (t0 + tt) < 200;
    float2 acc[5][2] = {};

    for (int ci0 = 0; ci0 < 512; ci0 += 32) {
        __syncthreads();
        for (int idx = tid; idx < 2048; idx += 256) {
            int cc = idx >> 6, j = idx & 63;
            int t = t0 + j;
            float v = (t < 200) ? x[((size_t)(b * 512) + ci0 + cc) * 200 + t] : 0.f;
            ((float2*)sx)[idx] = make_float2(v, v);
        }
        for (int idx = tid; idx < 2560; idx += 256)
            sw[idx] = wT[(size_t)ci0 * 80 + idx];
        __syncthreads();
        if (active) {
            #pragma unroll 8
            for (int cc = 0; cc < 32; cc++) {
                float4 xd = *(const float4*)&sx[cc * 128 + 2 * tt];
                float2 x0 = { xd.x, xd.y }, x1 = { xd.z, xd.w };
                const float2* wp = (const float2*)&sw[cc * 80 + cb];
                #pragma unroll
                for (int p = 0; p < 5; p++) {
                    float2 wd = wp[p];
                    acc[p][0] = ffma2(wd, x0, acc[p][0]);
                    acc[p][1] = ffma2(wd, x1, acc[p][1]);
                }
            }
        }
    }
    if (active) {
        #pragma unroll
        for (int p = 0; p < 5; p++) {
            int co = cb + 2 * p;
            float2 bv = *(const float2*)&bias[co];
            float2 v0 = { acc[p][0].x + bv.x, acc[p][1].x + bv.x };
            float2 v1 = { acc[p][0].y + bv.y, acc[p][1].y + bv.y };
            *(float2*)&y[((size_t)(b * 80) + co    ) * 200 + t0 + tt] = v0;
            *(float2*)&y[((size_t)(b * 80) + co + 1) * 200 + t0 + tt] = v1;
        }
    }
}

__device__ __forceinline__ void qchain_body(
    const float* __restrict__ x, const float* __restrict__ w2T, const float* __restrict__ b2,
    const float* __restrict__ w3T, const float* __restrict__ b3,
    float* __restrict__ y, int b, int t_tile, float* smem)
{
    float* sxd = smem;           // 8192 floats (32 x 128 dup'd, row 256)
    float* sw  = smem + 8192;    // 2560
    float* sh2 = smem + 10752;   // 80*128
    const int tid = threadIdx.x;
    const int cg = tid & 7, tg = tid >> 3;
    const int tt = tg * 4, cb = cg * 10;
    const int t0 = t_tile * 128;
    const bool active = (t0 + tt) < 800;

    {   // phase 1: h2 = relu(W2 x + b2), CIN=160, x dup'd
        float2 acc[5][4] = {};
        for (int ci0 = 0; ci0 < 160; ci0 += 32) {
            __syncthreads();
            for (int idx = tid; idx < 4096; idx += 256) {
                int cc = idx >> 7, j = idx & 127;
                int t = t0 + j;
                float v = (t < 800) ? x[((size_t)(b * 160) + ci0 + cc) * 800 + t] : 0.f;
                ((float2*)sxd)[idx] = make_float2(v, v);
            }
            for (int idx = tid; idx < 2560; idx += 256)
                sw[idx] = w2T[(size_t)ci0 * 80 + idx];
            __syncthreads();
            if (active) {
                #pragma unroll 8
                for (int cc = 0; cc < 32; cc++) {
                    const float* xr = &sxd[cc * 256 + 2 * tt];
                    float4 xd0 = *(const float4*)(xr);
                    float4 xd1 = *(const float4*)(xr + 4);
                    float2 xv[4] = { {xd0.x,xd0.y},{xd0.z,xd0.w},
                                     {xd1.x,xd1.y},{xd1.z,xd1.w} };
                    const float2* wp = (const float2*)&sw[cc * 80 + cb];
                    #pragma unroll
                    for (int p = 0; p < 5; p++) {
                        float2 wd = wp[p];
                        #pragma unroll
                        for (int u = 0; u < 4; u++)
                            acc[p][u] = ffma2(wd, xv[u], acc[p][u]);
                    }
                }
            }
        }
        if (active) {
            #pragma unroll
            for (int p = 0; p < 5; p++) {
                int co = cb + 2 * p;
                float2 bv = *(const float2*)&b2[co];
                float4 v0 = { fmaxf(acc[p][0].x + bv.x, 0.f), fmaxf(acc[p][1].x + bv.x, 0.f),
                              fmaxf(acc[p][2].x + bv.x, 0.f), fmaxf(acc[p][3].x + bv.x, 0.f) };
                float4 v1 = { fmaxf(acc[p][0].y + bv.y, 0.f), fmaxf(acc[p][1].y + bv.y, 0.f),
                              fmaxf(acc[p][2].y + bv.y, 0.f), fmaxf(acc[p][3].y + bv.y, 0.f) };
                *(float4*)&sh2[(co    ) * 128 + tt] = v0;
                *(float4*)&sh2[(co + 1) * 128 + tt] = v1;
            }
        }
    }
    {   // phase 2: q = W3 h2 + b3, CIN=80 (h2 in smem, non-dup)
        float2 acc[5][4] = {};
        for (int ci0 = 0; ci0 < 80; ci0 += 32) {
            const int CC = (80 - ci0 < 32) ? (80 - ci0) : 32;
            __syncthreads();
            for (int idx = tid; idx < CC * 80; idx += 256)
                sw[idx] = w3T[(size_t)ci0 * 80 + idx];
            __syncthreads();
            if (active) fma1x1_chunk(&sh2[ci0 * 128], sw, tt, cb, CC, acc);
        }
        if (active) {
            #pragma unroll
            for (int p = 0; p < 5; p++) {
                int co = cb + 2 * p;
                float2 bv = *(const float2*)&b3[co];
                float4 v0 = { acc[p][0].x + bv.x, acc[p][1].x + bv.x,
                              acc[p][2].x + bv.x, acc[p][3].x + bv.x };
                float4 v1 = { acc[p][0].y + bv.y, acc[p][1].y + bv.y,
                              acc[p][2].y + bv.y, acc[p][3].y + bv.y };
                *(float4*)&y[((size_t)(b * 80) + co    ) * 800 + t0 + tt] = v0;
                *(float4*)&y[((size_t)(b * 80) + co + 1) * 800 + t0 + tt] = v1;
            }
        }
    }
}

__global__ void stageB_kernel(
    const float* __restrict__ k1in, const float* __restrict__ kb2, float* __restrict__ kout,
    const float* __restrict__ q1in, const float* __restrict__ qb2,
    const float* __restrict__ qb3, float* __restrict__ qout)
{
    extern __shared__ float smem[];
    int id = blockIdx.x;
    if (id < 64) key1x1_body(k1in, g_kw2T, kb2, kout, id >> 2, id & 3, smem);
    else {
        int j = id - 64;
        qchain_body(q1in, g_qw2T, qb2, g_qw3T, qb3, qout, j / 7, j % 7, smem);
    }
}

// =================== STAGE C: L2-dist + log_softmax + log(prior) ==========
// grid (50,16), block 256, t1 tile 16. q stored dup'd; accumulate s-pairs so
// k-pairs alias the LDG.128 halves -> zero MOVs in inner loop.
__global__ void attention_kernel(const float* __restrict__ q, const float* __restrict__ k,
                                 const float* __restrict__ prior, float* __restrict__ out)
{
    extern __shared__ float smem[];
    float* sq = smem;              // 80*32 (dup'd, row = 16 float2)
    float* sd = smem + 2560;       // 16*200

    const int b    = blockIdx.y;
    const int t1_0 = blockIdx.x * 16;
    const int tid  = threadIdx.x;

    for (int idx = tid; idx < 1280; idx += 256) {
        int c = idx >> 4, j = idx & 15;
        float v = q[((size_t)(b * 80) + c) * 800 + t1_0 + j];
        ((float2*)sq)[idx] = make_float2(v, v);
    }
    __syncthreads();

    const int sg = tid & 63, jg = tid >> 6;
    if (sg < 50) {
        const int s0 = sg * 4, j0 = jg * 4;
        const float* kp = &k[(size_t)(b * 80) * 200 + s0];
        float2 acc[4][2] = {};      // [jj][spair]
        float2 k2p[2] = {}, q2p[4] = {};

        float4 kbuf[4];
        #pragma unroll
        for (int i = 0; i < 4; i++) kbuf[i] = *(const float4*)(kp + i * 200);

        #pragma unroll
        for (int c0 = 0; c0 < 80; c0 += 4) {
            float4 cur[4];
            #pragma unroll
            for (int i = 0; i < 4; i++) cur[i] = kbuf[i];
            if (c0 + 4 < 80) {
                #pragma unroll
                for (int i = 0; i < 4; i++)
                    kbuf[i] = *(const float4*)(kp + (c0 + 4 + i) * 200);
            }
            #pragma unroll
            for (int i = 0; i < 4; i++) {
                int c = c0 + i;
                float4 kq = cur[i];
                float2 kp01 = { kq.x, kq.y }, kp23 = { kq.z, kq.w };
                const float* qr = &sq[c * 32 + 2 * j0];
                float4 qd0 = *(const float4*)(qr);
                float4 qd1 = *(const float4*)(qr + 4);
                float2 qd[4] = { {qd0.x,qd0.y},{qd0.z,qd0.w},
                                 {qd1.x,qd1.y},{qd1.z,qd1.w} };
                k2p[0] = ffma2(kp01, kp01, k2p[0]);
                k2p[1] = ffma2(kp23, kp23, k2p[1]);
                #pragma unroll
                for (int jj = 0; jj < 4; jj++) {
                    q2p[jj]   = ffma2(qd[jj], qd[jj], q2p[jj]);
                    acc[jj][0] = ffma2(qd[jj], kp01, acc[jj][0]);
                    acc[jj][1] = ffma2(qd[jj], kp23, acc[jj][1]);
                }
            }
        }
        float k2s[4] = { k2p[0].x, k2p[0].y, k2p[1].x, k2p[1].y };
        #pragma unroll
        for (int jj = 0; jj < 4; jj++) {
            float q2 = q2p[jj].x;
            float4 v = { -0.0005f * (q2 + k2s[0] - 2.f * acc[jj][0].x),
                         -0.0005f * (q2 + k2s[1] - 2.f * acc[jj][0].y),
                         -0.0005f * (q2 + k2s[2] - 2.f * acc[jj][1].x),
                         -0.0005f * (q2 + k2s[3] - 2.f * acc[jj][1].y) };
            *(float4*)&sd[(j0 + jj) * 200 + s0] = v;
        }
    }
    __syncthreads();

    const int warp = tid >> 5, lane = tid & 31;
    #pragma unroll
    for (int rr = 0; rr < 2; rr++) {
        int j = warp + rr * 8;
        const float* pr = &prior[((size_t)b * 800 + t1_0 + j) * 200];
        float prv[7];
        #pragma unroll
        for (int i = 0; i < 7; i++) {
            int s = lane + 32 * i;
            prv[i] = (s < 200) ? pr[s] : 1.f;
        }
        float m = -1e30f;
        #pragma unroll
        for (int i = 0; i < 7; i++) {
            int s = lane + 32 * i;
            if (s < 200) m = fmaxf(m, sd[j * 200 + s]);
        }
        #pragma unroll
        for (int o = 16; o; o >>= 1) m = fmaxf(m, __shfl_xor_sync(0xffffffffu, m, o));
        float sum = 0.f;
        #pragma unroll
        for (int i = 0; i < 7; i++) {
            int s = lane + 32 * i;
            if (s < 200) sum += __expf(sd[j * 200 + s] - m);
        }
        #pragma unroll
        for (int o = 16; o; o >>= 1) sum += __shfl_xor_sync(0xffffffffu, sum, o);
        float lse = m + __logf(sum);
        float* op = &out[((size_t)b * 800 + t1_0 + j) * 200];
        #pragma unroll
        for (int i = 0; i < 7; i++) {
            int s = lane + 32 * i;
            if (s < 200) op[s] = sd[j * 200 + s] - lse + __logf(prv[i] + 1e-8f);
        }
    }
}

// -------------------------------- launch ---------------------------------
extern "C" void kernel_launch(void* const* d_in, const int* in_sizes, int n_in,
                              void* d_out, int out_size)
{
    const float* queries = (const float*)d_in[0];
    const float* keys    = (const float*)d_in[1];
    const float* prior   = (const float*)d_in[2];
    const float* kw1 = (const float*)d_in[3];
    const float* kb1 = (const float*)d_in[4];
    const float* kw2 = (const float*)d_in[5];
    const float* kb2 = (const float*)d_in[6];
    const float* qw1 = (const float*)d_in[7];
    const float* qb1 = (const float*)d_in[8];
    const float* qw2 = (const float*)d_in[9];
    const float* qb2 = (const float*)d_in[10];
    const float* qw3 = (const float*)d_in[11];
    const float* qb3 = (const float*)d_in[12];
    float* out = (float*)d_out;

    float *k1buf, *kbuf, *q1buf, *qbuf;
    float *kw1T, *qw1T, *kw2T, *qw2T, *qw3T;
    cudaGetSymbolAddress((void**)&k1buf, g_k1);
    cudaGetSymbolAddress((void**)&kbuf,  g_k);
    cudaGetSymbolAddress((void**)&q1buf, g_q1);
    cudaGetSymbolAddress((void**)&qbuf,  g_qf);
    cudaGetSymbolAddress((void**)&kw1T, g_kw1T);
    cudaGetSymbolAddress((void**)&qw1T, g_qw1T);
    cudaGetSymbolAddress((void**)&kw2T, g_kw2T);
    cudaGetSymbolAddress((void**)&qw2T, g_qw2T);
    cudaGetSymbolAddress((void**)&qw3T, g_qw3T);

    const int smem_A    = (16 * 136 + 48 * 160) * 4;             // 39424
    const int smem_B    = (8192 + 2560 + 80 * 128) * 4;          // 83968
    const int smem_attn = (2560 + 16 * 200) * 4;                 // 23040

    cudaFuncSetAttribute((const void*)stageA_kernel,
                         cudaFuncAttributeMaxDynamicSharedMemorySize, smem_A);
    cudaFuncSetAttribute((const void*)stageB_kernel,
                         cudaFuncAttributeMaxDynamicSharedMemorySize, smem_B);
    cudaFuncSetAttribute((const void*)attention_kernel,
                         cudaFuncAttributeMaxDynamicSharedMemorySize, smem_attn);

    prep_kernel<<<1921, 256>>>(kw1, qw1, kw2, qw2, qw3, kw1T, qw1T, kw2T, qw2T, qw3T);
    stageA_kernel<<<720, 256, smem_A>>>(keys, kb1, queries, qb1, k1buf, q1buf);
    stageB_kernel<<<176, 256, smem_B>>>(k1buf, kb2, kbuf, q1buf, qb2, qb3, qbuf);
    attention_kernel<<<dim3(50, 16), 256, smem_attn>>>(qbuf, kbuf, prior, out);
}

// round 11
// speedup vs baseline: 1.0942x; 1.0942x over previous
#include <cuda_runtime.h>
#include <math.h>

// ---------------- scratch (device globals; no allocation) ----------------
__device__ float g_k1  [16 * 512 * 200];   // key conv1 out
__device__ float g_k   [16 *  80 * 200];   // key encoder out
__device__ float g_q1  [16 * 160 * 800];   // query conv1 out
__device__ float g_qf  [16 *  80 * 800];   // query encoder out
__device__ float g_kw1T[768 * 512];        // kw1 transposed [(ci*3+k)][co]
__device__ float g_qw1T[240 * 160];
__device__ float g_kw2T[512 *  80];        // kw2 transposed [ci][co]
__device__ float g_qw2T[160 *  80];
__device__ float g_qw3T[ 80 *  80];

// ---------------- packed fp32x2 FMA (Blackwell) ---------------------------
__device__ __forceinline__ float2 ffma2(float2 a, float2 b, float2 c) {
    unsigned long long ua = *reinterpret_cast<unsigned long long*>(&a);
    unsigned long long ub = *reinterpret_cast<unsigned long long*>(&b);
    unsigned long long uc = *reinterpret_cast<unsigned long long*>(&c);
    unsigned long long ud;
    asm("fma.rn.f32x2 %0, %1, %2, %3;" : "=l"(ud) : "l"(ua), "l"(ub), "l"(uc));
    return *reinterpret_cast<float2*>(&ud);
}
__device__ __forceinline__ float2 dup(float v) { return make_float2(v, v); }

// =================== PREP: tiled (coalesced) weight transposes ============
// dst[c*R + r] = src[r*C + c] for each weight matrix, 32x32 smem tiles.
__global__ void prep_kernel(const float* __restrict__ kw1, const float* __restrict__ qw1,
                            const float* __restrict__ kw2, const float* __restrict__ qw2,
                            const float* __restrict__ qw3,
                            float* __restrict__ kw1T, float* __restrict__ qw1T,
                            float* __restrict__ kw2T, float* __restrict__ qw2T,
                            float* __restrict__ qw3T)
{
    __shared__ float tile[32][33];
    int id = blockIdx.x;
    const float* src; float* dst; int R, C, bi, bj;
    if (id < 384)            { src = kw1; dst = kw1T; R = 512; C = 768; bi = id / 24; bj = id % 24; }
    else if ((id -= 384) < 40) { src = qw1; dst = qw1T; R = 160; C = 240; bi = id / 8;  bj = id % 8;  }
    else if ((id -= 40) < 48)  { src = kw2; dst = kw2T; R = 80;  C = 512; bi = id / 16; bj = id % 16; }
    else if ((id -= 48) < 15)  { src = qw2; dst = qw2T; R = 80;  C = 160; bi = id / 5;  bj = id % 5;  }
    else      { id -= 15;        src = qw3; dst = qw3T; R = 80;  C = 80;  bi = id / 3;  bj = id % 3;  }

    const int r0 = bi * 32, c0 = bj * 32;
    const int tx = threadIdx.x & 31, ty = threadIdx.x >> 5;   // 32 x 8

    #pragma unroll
    for (int yy = ty; yy < 32; yy += 8) {
        int r = r0 + yy, c = c0 + tx;
        tile[yy][tx] = (r < R && c < C) ? src[(size_t)r * C + c] : 0.f;
    }
    __syncthreads();
    #pragma unroll
    for (int yy = ty; yy < 32; yy += 8) {
        int c = c0 + yy, r = r0 + tx;
        if (c < C && r < R) dst[(size_t)c * R + r] = tile[tx][yy];
    }
}

// =================== STAGE A: both k=3 pad=1 convs (R9 exact) =============
template<int CIN, int COUT, int TLEN, int CPAIRS, int CICH>
__device__ __forceinline__ void conv3_body(
    const float* __restrict__ x, const float* __restrict__ wT,
    const float* __restrict__ bias, float* __restrict__ y,
    int b, int t_tile, int co_tile, float* smem)
{
    constexpr int COT = 32 * CPAIRS;
    constexpr int NW4 = CICH * 3 * COT / 4;
    float* sx = smem;                   // CICH * 68
    float* sw = smem + CICH * 68;       // CICH*3*COT

    const int tid = threadIdx.x;
    const int cg = tid & 15, tg = tid >> 4;
    const int tt = tg * 4, ct = cg * 2 * CPAIRS;
    const int t0 = t_tile * 64, co0 = co_tile * COT;
    const bool active = (t0 + tt) < TLEN;

    float2 acc[CPAIRS][4] = {};

    for (int ci0 = 0; ci0 < CIN; ci0 += CICH) {
        __syncthreads();
        for (int idx = tid; idx < CICH * 66; idx += 256) {
            int cc = idx / 66, j = idx - cc * 66;
            int t = t0 + j - 1;
            sx[cc * 68 + j] = (t >= 0 && t < TLEN)
                ? x[((size_t)(b * CIN) + ci0 + cc) * TLEN + t] : 0.f;
        }
        for (int idx = tid; idx < NW4; idx += 256) {
            int r = idx / (COT / 4), c4 = idx - r * (COT / 4);
            ((float4*)sw)[idx] =
                *(const float4*)&wT[(size_t)(ci0 * 3 + r) * COUT + co0 + c4 * 4];
        }
        __syncthreads();
        if (active) {
            #pragma unroll
            for (int cc = 0; cc < CICH; cc++) {
                const float* xr = &sx[cc * 68 + tt];
                float4 xa = *(const float4*)xr;
                float2 xb = *(const float2*)(xr + 4);
                float2 xv[6] = { dup(xa.x), dup(xa.y), dup(xa.z),
                                 dup(xa.w), dup(xb.x), dup(xb.y) };
                float2 wk[3][CPAIRS];
                #pragma unroll
                for (int k = 0; k < 3; k++) {
                    const float* wb = &sw[(cc * 3 + k) * COT + ct];
                    if constexpr ((CPAIRS & 1) == 0) {
                        #pragma unroll
                        for (int q = 0; q < CPAIRS / 2; q++) {
                            float4 wv = *(const float4*)(wb + 4 * q);
                            wk[k][2*q]   = make_float2(wv.x, wv.y);
                            wk[k][2*q+1] = make_float2(wv.z, wv.w);
                        }
                    } else {
                        #pragma unroll
                        for (int p = 0; p < CPAIRS; p++)
                            wk[k][p] = *(const float2*)(wb + 2 * p);
                    }
                }
                #pragma unroll
                for (int u = 0; u < 4; u++)
                    #pragma unroll
                    for (int p = 0; p < CPAIRS; p++)
                        acc[p][u] = ffma2(wk[0][p], xv[u],
                                    ffma2(wk[1][p], xv[u+1],
                                    ffma2(wk[2][p], xv[u+2], acc[p][u])));
            }
        }
    }

    if (active) {
        #pragma unroll
        for (int p = 0; p < CPAIRS; p++) {
            int co = co0 + ct + 2 * p;
            float2 bv = *(const float2*)&bias[co];
            float4 v0 = { fmaxf(acc[p][0].x + bv.x, 0.f), fmaxf(acc[p][1].x + bv.x, 0.f),
                          fmaxf(acc[p][2].x + bv.x, 0.f), fmaxf(acc[p][3].x + bv.x, 0.f) };
            float4 v1 = { fmaxf(acc[p][0].y + bv.y, 0.f), fmaxf(acc[p][1].y + bv.y, 0.f),
                          fmaxf(acc[p][2].y + bv.y, 0.f), fmaxf(acc[p][3].y + bv.y, 0.f) };
            *(float4*)&y[((size_t)(b * COUT) + co    ) * TLEN + t0 + tt] = v0;
            *(float4*)&y[((size_t)(b * COUT) + co + 1) * TLEN + t0 + tt] = v1;
        }
    }
}

__global__ void __launch_bounds__(256)
stageA_kernel(
    const float* __restrict__ keys, const float* __restrict__ kb1,
    const float* __restrict__ queries, const float* __restrict__ qb1,
    float* __restrict__ k1out, float* __restrict__ q1out)
{
    extern __shared__ float smem[];
    int id = blockIdx.x;
    if (id < 512) {
        int b = id >> 5, r = id & 31;
        conv3_body<256, 512, 200, 2, 16>(keys, g_kw1T, kb1, k1out,
                                         b, r & 3, r >> 2, smem);
    } else {
        int j = id - 512;
        conv3_body<80, 160, 800, 5, 16>(queries, g_qw1T, qb1, q1out,
                                        j / 13, j % 13, 0, smem);
    }
}

// =================== STAGE B: key 1x1 + qchain (both t-tile 64) ===========
// key 1x1: t-tile 64, 64 blocks. 256 thr = 8 cg x 32 tg, 10co x 2t. (R9 exact)
__device__ __forceinline__ void key1x1_body(
    const float* __restrict__ x, const float* __restrict__ wT,
    const float* __restrict__ bias, float* __restrict__ y,
    int b, int t_tile, float* smem)
{
    float* sx = smem;          // 32*64
    float* sw = smem + 2048;   // 32*80
    const int tid = threadIdx.x;
    const int cg = tid & 7, tg = tid >> 3;
    const int tt = tg * 2, cb = cg * 10;
    const int t0 = t_tile * 64;
    const bool active = (t0 + tt) < 200;
    float2 acc[5][2] = {};

    for (int ci0 = 0; ci0 < 512; ci0 += 32) {
        __syncthreads();
        for (int idx = tid; idx < 2048; idx += 256) {
            int cc = idx >> 6, j = idx & 63;
            int t = t0 + j;
            sx[idx] = (t < 200) ? x[((size_t)(b * 512) + ci0 + cc) * 200 + t] : 0.f;
        }
        for (int idx = tid; idx < 2560; idx += 256)
            sw[idx] = wT[(size_t)ci0 * 80 + idx];
        __syncthreads();
        if (active) {
            #pragma unroll 8
            for (int cc = 0; cc < 32; cc++) {
                float2 xq = *(const float2*)&sx[cc * 64 + tt];
                float2 x0 = dup(xq.x), x1 = dup(xq.y);
                const float2* wp = (const float2*)&sw[cc * 80 + cb];
                #pragma unroll
                for (int p = 0; p < 5; p++) {
                    float2 wd = wp[p];
                    acc[p][0] = ffma2(wd, x0, acc[p][0]);
                    acc[p][1] = ffma2(wd, x1, acc[p][1]);
                }
            }
        }
    }
    if (active) {
        #pragma unroll
        for (int p = 0; p < 5; p++) {
            int co = cb + 2 * p;
            float2 bv = *(const float2*)&bias[co];
            float2 v0 = { acc[p][0].x + bv.x, acc[p][1].x + bv.x };
            float2 v1 = { acc[p][0].y + bv.y, acc[p][1].y + bv.y };
            *(float2*)&y[((size_t)(b * 80) + co    ) * 200 + t0 + tt] = v0;
            *(float2*)&y[((size_t)(b * 80) + co + 1) * 200 + t0 + tt] = v1;
        }
    }
}

// qchain: t-tile 64 (was 128). 13 tiles x 16 b = 208 blocks. 10co x 2t.
// smem: sx[32][64] + sw[32*80] + sh2[80][64] = 9728 floats (38.9 KB)
__device__ __forceinline__ void qchain_body(
    const float* __restrict__ x, const float* __restrict__ w2T, const float* __restrict__ b2,
    const float* __restrict__ w3T, const float* __restrict__ b3,
    float* __restrict__ y, int b, int t_tile, float* smem)
{
    float* sx  = smem;          // 2048
    float* sw  = smem + 2048;   // 2560
    float* sh2 = smem + 4608;   // 5120
    const int tid = threadIdx.x;
    const int cg = tid & 7, tg = tid >> 3;
    const int tt = tg * 2, cb = cg * 10;
    const int t0 = t_tile * 64;
    const bool active = (t0 + tt) < 800;

    {   // phase 1: h2 = relu(W2 x + b2), CIN=160 -> sh2
        float2 acc[5][2] = {};
        for (int ci0 = 0; ci0 < 160; ci0 += 32) {
            __syncthreads();
            for (int idx = tid; idx < 2048; idx += 256) {
                int cc = idx >> 6, j = idx & 63;
                int t = t0 + j;
                sx[idx] = (t < 800) ? x[((size_t)(b * 160) + ci0 + cc) * 800 + t] : 0.f;
            }
            for (int idx = tid; idx < 2560; idx += 256)
                sw[idx] = w2T[(size_t)ci0 * 80 + idx];
            __syncthreads();
            if (active) {
                #pragma unroll 8
                for (int cc = 0; cc < 32; cc++) {
                    float2 xq = *(const float2*)&sx[cc * 64 + tt];
                    float2 x0 = dup(xq.x), x1 = dup(xq.y);
                    const float2* wp = (const float2*)&sw[cc * 80 + cb];
                    #pragma unroll
                    for (int p = 0; p < 5; p++) {
                        float2 wd = wp[p];
                        acc[p][0] = ffma2(wd, x0, acc[p][0]);
                        acc[p][1] = ffma2(wd, x1, acc[p][1]);
                    }
                }
            }
        }
        if (active) {
            #pragma unroll
            for (int p = 0; p < 5; p++) {
                int co = cb + 2 * p;
                float2 bv = *(const float2*)&b2[co];
                float2 v0 = { fmaxf(acc[p][0].x + bv.x, 0.f), fmaxf(acc[p][1].x + bv.x, 0.f) };
                float2 v1 = { fmaxf(acc[p][0].y + bv.y, 0.f), fmaxf(acc[p][1].y + bv.y, 0.f) };
                *(float2*)&sh2[(co    ) * 64 + tt] = v0;
                *(float2*)&sh2[(co + 1) * 64 + tt] = v1;
            }
        }
    }
    {   // phase 2: q = W3 h2 + b3, CIN=80 (h2 in smem)
        float2 acc[5][2] = {};
        for (int ci0 = 0; ci0 < 80; ci0 += 32) {
            const int CC = (80 - ci0 < 32) ? (80 - ci0) : 32;
            __syncthreads();
            for (int idx = tid; idx < CC * 80; idx += 256)
                sw[idx] = w3T[(size_t)ci0 * 80 + idx];
            __syncthreads();
            if (active) {
                #pragma unroll 8
                for (int cc = 0; cc < CC; cc++) {
                    float2 xq = *(const float2*)&sh2[(ci0 + cc) * 64 + tt];
                    float2 x0 = dup(xq.x), x1 = dup(xq.y);
                    const float2* wp = (const float2*)&sw[cc * 80 + cb];
                    #pragma unroll
                    for (int p = 0; p < 5; p++) {
                        float2 wd = wp[p];
                        acc[p][0] = ffma2(wd, x0, acc[p][0]);
                        acc[p][1] = ffma2(wd, x1, acc[p][1]);
                    }
                }
            }
        }
        if (active) {
            #pragma unroll
            for (int p = 0; p < 5; p++) {
                int co = cb + 2 * p;
                float2 bv = *(const float2*)&b3[co];
                float2 v0 = { acc[p][0].x + bv.x, acc[p][1].x + bv.x };
                float2 v1 = { acc[p][0].y + bv.y, acc[p][1].y + bv.y };
                *(float2*)&y[((size_t)(b * 80) + co    ) * 800 + t0 + tt] = v0;
                *(float2*)&y[((size_t)(b * 80) + co + 1) * 800 + t0 + tt] = v1;
            }
        }
    }
}

__global__ void stageB_kernel(
    const float* __restrict__ k1in, const float* __restrict__ kb2, float* __restrict__ kout,
    const float* __restrict__ q1in, const float* __restrict__ qb2,
    const float* __restrict__ qb3, float* __restrict__ qout)
{
    extern __shared__ float smem[];
    int id = blockIdx.x;
    if (id < 64) key1x1_body(k1in, g_kw2T, kb2, kout, id >> 2, id & 3, smem);
    else {
        int j = id - 64;
        qchain_body(q1in, g_qw2T, qb2, g_qw3T, qb3, qout, j / 13, j % 13, smem);
    }
}

// =================== STAGE C: attention (R8/R9 exact) =====================
__global__ void attention_kernel(const float* __restrict__ q, const float* __restrict__ k,
                                 const float* __restrict__ prior, float* __restrict__ out)
{
    extern __shared__ float smem[];
    float* sq = smem;              // 80*16
    float* sd = smem + 1280;       // 16*200

    const int b    = blockIdx.y;
    const int t1_0 = blockIdx.x * 16;
    const int tid  = threadIdx.x;

    {
        int i = tid;
        if (i < 320) {
            int c = i >> 2, jq = (i & 3) << 2;
            *(float4*)&sq[c * 16 + jq] =
                *(const float4*)&q[((size_t)(b * 80) + c) * 800 + t1_0 + jq];
        }
        i = tid + 256;
        if (i < 320) {
            int c = i >> 2, jq = (i & 3) << 2;
            *(float4*)&sq[c * 16 + jq] =
                *(const float4*)&q[((size_t)(b * 80) + c) * 800 + t1_0 + jq];
        }
    }
    __syncthreads();

    const int sg = tid & 63, jg = tid >> 6;
    if (sg < 50) {
        const int s0 = sg * 4, j0 = jg * 4;
        const float* kp = &k[(size_t)(b * 80) * 200 + s0];
        float2 acc[4][2] = {};
        float2 k2p[2] = {}, q2p[2] = {};

        float4 kbuf[4];
        #pragma unroll
        for (int i = 0; i < 4; i++) kbuf[i] = *(const float4*)(kp + i * 200);

        #pragma unroll
        for (int c0 = 0; c0 < 80; c0 += 4) {
            float4 cur[4];
            #pragma unroll
            for (int i = 0; i < 4; i++) cur[i] = kbuf[i];
            if (c0 + 4 < 80) {
                #pragma unroll
                for (int i = 0; i < 4; i++)
                    kbuf[i] = *(const float4*)(kp + (c0 + 4 + i) * 200);
            }
            #pragma unroll
            for (int i = 0; i < 4; i++) {
                int c = c0 + i;
                float4 kq = cur[i];
                float4 qa = *(const float4*)&sq[c * 16 + j0];
                float2 qp[2] = { {qa.x, qa.y}, {qa.z, qa.w} };
                float2 kpair0 = { kq.x, kq.y }, kpair1 = { kq.z, kq.w };
                k2p[0] = ffma2(kpair0, kpair0, k2p[0]);
                k2p[1] = ffma2(kpair1, kpair1, k2p[1]);
                q2p[0] = ffma2(qp[0], qp[0], q2p[0]);
                q2p[1] = ffma2(qp[1], qp[1], q2p[1]);
                float ks[4] = { kq.x, kq.y, kq.z, kq.w };
                #pragma unroll
                for (int si = 0; si < 4; si++) {
                    float2 kd = dup(ks[si]);
                    acc[si][0] = ffma2(kd, qp[0], acc[si][0]);
                    acc[si][1] = ffma2(kd, qp[1], acc[si][1]);
                }
            }
        }
        float k2s[4] = { k2p[0].x, k2p[0].y, k2p[1].x, k2p[1].y };
        float q2s[4] = { q2p[0].x, q2p[0].y, q2p[1].x, q2p[1].y };
        #pragma unroll
        for (int jj = 0; jj < 4; jj++) {
            int p = jj >> 1;
            float a0 = (jj & 1) ? acc[0][p].y : acc[0][p].x;
            float a1 = (jj & 1) ? acc[1][p].y : acc[1][p].x;
            float a2 = (jj & 1) ? acc[2][p].y : acc[2][p].x;
            float a3 = (jj & 1) ? acc[3][p].y : acc[3][p].x;
            float4 v = { -0.0005f * (q2s[jj] + k2s[0] - 2.f * a0),
                         -0.0005f * (q2s[jj] + k2s[1] - 2.f * a1),
                         -0.0005f * (q2s[jj] + k2s[2] - 2.f * a2),
                         -0.0005f * (q2s[jj] + k2s[3] - 2.f * a3) };
            *(float4*)&sd[(j0 + jj) * 200 + s0] = v;
        }
    }
    __syncthreads();

    const int warp = tid >> 5, lane = tid & 31;
    #pragma unroll
    for (int rr = 0; rr < 2; rr++) {
        int j = warp + rr * 8;
        const float* pr = &prior[((size_t)b * 800 + t1_0 + j) * 200];
        float prv[7];
        #pragma unroll
        for (int i = 0; i < 7; i++) {
            int s = lane + 32 * i;
            prv[i] = (s < 200) ? pr[s] : 1.f;
        }
        float m = -1e30f;
        #pragma unroll
        for (int i = 0; i < 7; i++) {
            int s = lane + 32 * i;
            if (s < 200) m = fmaxf(m, sd[j * 200 + s]);
        }
        #pragma unroll
        for (int o = 16; o; o >>= 1) m = fmaxf(m, __shfl_xor_sync(0xffffffffu, m, o));
        float sum = 0.f;
        #pragma unroll
        for (int i = 0; i < 7; i++) {
            int s = lane + 32 * i;
            if (s < 200) sum += __expf(sd[j * 200 + s] - m);
        }
        #pragma unroll
        for (int o = 16; o; o >>= 1) sum += __shfl_xor_sync(0xffffffffu, sum, o);
        float lse = m + __logf(sum);
        float* op = &out[((size_t)b * 800 + t1_0 + j) * 200];
        #pragma unroll
        for (int i = 0; i < 7; i++) {
            int s = lane + 32 * i;
            if (s < 200) op[s] = sd[j * 200 + s] - lse + __logf(prv[i] + 1e-8f);
        }
    }
}

// -------------------------------- launch ---------------------------------
extern "C" void kernel_launch(void* const* d_in, const int* in_sizes, int n_in,
                              void* d_out, int out_size)
{
    const float* queries = (const float*)d_in[0];
    const float* keys    = (const float*)d_in[1];
    const float* prior   = (const float*)d_in[2];
    const float* kw1 = (const float*)d_in[3];
    const float* kb1 = (const float*)d_in[4];
    const float* kw2 = (const float*)d_in[5];
    const float* kb2 = (const float*)d_in[6];
    const float* qw1 = (const float*)d_in[7];
    const float* qb1 = (const float*)d_in[8];
    const float* qw2 = (const float*)d_in[9];
    const float* qb2 = (const float*)d_in[10];
    const float* qw3 = (const float*)d_in[11];
    const float* qb3 = (const float*)d_in[12];
    float* out = (float*)d_out;

    float *k1buf, *kbuf, *q1buf, *qbuf;
    float *kw1T, *qw1T, *kw2T, *qw2T, *qw3T;
    cudaGetSymbolAddress((void**)&k1buf, g_k1);
    cudaGetSymbolAddress((void**)&kbuf,  g_k);
    cudaGetSymbolAddress((void**)&q1buf, g_q1);
    cudaGetSymbolAddress((void**)&qbuf,  g_qf);
    cudaGetSymbolAddress((void**)&kw1T, g_kw1T);
    cudaGetSymbolAddress((void**)&qw1T, g_qw1T);
    cudaGetSymbolAddress((void**)&kw2T, g_kw2T);
    cudaGetSymbolAddress((void**)&qw2T, g_qw2T);
    cudaGetSymbolAddress((void**)&qw3T, g_qw3T);

    const int smem_A    = (16 * 68 + 48 * 160) * 4;              // 35072
    const int smem_B    = 9728 * 4;                              // 38912
    const int smem_attn = (1280 + 16 * 200) * 4;                 // 17920

    cudaFuncSetAttribute((const void*)stageA_kernel,
                         cudaFuncAttributeMaxDynamicSharedMemorySize, smem_A);
    cudaFuncSetAttribute((const void*)stageB_kernel,
                         cudaFuncAttributeMaxDynamicSharedMemorySize, smem_B);

    prep_kernel<<<496, 256>>>(kw1, qw1, kw2, qw2, qw3, kw1T, qw1T, kw2T, qw2T, qw3T);
    stageA_kernel<<<720, 256, smem_A>>>(keys, kb1, queries, qb1, k1buf, q1buf);
    stageB_kernel<<<272, 256, smem_B>>>(k1buf, kb2, kbuf, q1buf, qb2, qb3, qbuf);
    attention_kernel<<<dim3(50, 16), 256, smem_attn>>>(qbuf, kbuf, prior, out);
}

// round 13
// speedup vs baseline: 1.2263x; 1.1208x over previous
#include <cuda_runtime.h>
#include <cstdint>
#include <math.h>

// ---------------- scratch (device globals; no allocation) ----------------
__device__ float g_k1  [16 * 512 * 200];   // key conv1 out
__device__ float g_k   [16 *  80 * 200];   // key encoder out
__device__ float g_q1  [16 * 160 * 800];   // query conv1 out
__device__ float g_qf  [16 *  80 * 800];   // query encoder out
__device__ float g_kw1T[768 * 512];        // kw1 transposed [(ci*3+k)][co]
__device__ float g_qw1T[240 * 160];
__device__ float g_kw2T[512 *  80];        // kw2 transposed [ci][co]
__device__ float g_qw2T[160 *  80];
__device__ float g_qw3T[ 80 *  80];

// ---------------- packed fp32x2 FMA (Blackwell) ---------------------------
__device__ __forceinline__ float2 ffma2(float2 a, float2 b, float2 c) {
    unsigned long long ua = *reinterpret_cast<unsigned long long*>(&a);
    unsigned long long ub = *reinterpret_cast<unsigned long long*>(&b);
    unsigned long long uc = *reinterpret_cast<unsigned long long*>(&c);
    unsigned long long ud;
    asm("fma.rn.f32x2 %0, %1, %2, %3;" : "=l"(ud) : "l"(ua), "l"(ub), "l"(uc));
    return *reinterpret_cast<float2*>(&ud);
}
__device__ __forceinline__ float2 dup(float v) { return make_float2(v, v); }

// ---------------- cp.async helpers ----------------------------------------
__device__ __forceinline__ void cp_async4(void* dst, const void* src, bool pred) {
    unsigned int d = (unsigned int)__cvta_generic_to_shared(dst);
    int sz = pred ? 4 : 0;
    asm volatile("cp.async.ca.shared.global [%0], [%1], 4, %2;"
                 :: "r"(d), "l"(src), "r"(sz) : "memory");
}
__device__ __forceinline__ void cp_async16(void* dst, const void* src) {
    unsigned int d = (unsigned int)__cvta_generic_to_shared(dst);
    asm volatile("cp.async.ca.shared.global [%0], [%1], 16;"
                 :: "r"(d), "l"(src) : "memory");
}
#define CP_COMMIT() asm volatile("cp.async.commit_group;" ::: "memory")
#define CP_WAIT0()  asm volatile("cp.async.wait_group 0;" ::: "memory")

// =================== PREP: tiled (coalesced) weight transposes ============
__global__ void prep_kernel(const float* __restrict__ kw1, const float* __restrict__ qw1,
                            const float* __restrict__ kw2, const float* __restrict__ qw2,
                            const float* __restrict__ qw3,
                            float* __restrict__ kw1T, float* __restrict__ qw1T,
                            float* __restrict__ kw2T, float* __restrict__ qw2T,
                            float* __restrict__ qw3T)
{
    __shared__ float tile[32][33];
    int id = blockIdx.x;
    const float* src; float* dst; int R, C, bi, bj;
    if (id < 384)            { src = kw1; dst = kw1T; R = 512; C = 768; bi = id / 24; bj = id % 24; }
    else if ((id -= 384) < 40) { src = qw1; dst = qw1T; R = 160; C = 240; bi = id / 8;  bj = id % 8;  }
    else if ((id -= 40) < 48)  { src = kw2; dst = kw2T; R = 80;  C = 512; bi = id / 16; bj = id % 16; }
    else if ((id -= 48) < 15)  { src = qw2; dst = qw2T; R = 80;  C = 160; bi = id / 5;  bj = id % 5;  }
    else      { id -= 15;        src = qw3; dst = qw3T; R = 80;  C = 80;  bi = id / 3;  bj = id % 3;  }

    const int r0 = bi * 32, c0 = bj * 32;
    const int tx = threadIdx.x & 31, ty = threadIdx.x >> 5;

    #pragma unroll
    for (int yy = ty; yy < 32; yy += 8) {
        int r = r0 + yy, c = c0 + tx;
        tile[yy][tx] = (r < R && c < C) ? src[(size_t)r * C + c] : 0.f;
    }
    __syncthreads();
    #pragma unroll
    for (int yy = ty; yy < 32; yy += 8) {
        int c = c0 + yy, r = r0 + tx;
        if (c < C && r < R) dst[(size_t)c * R + r] = tile[tx][yy];
    }
}

// =================== STAGE A: conv3 with cp.async double buffering ========
// Per chunk: wait(stage i) -> 1 barrier -> issue stage(i+1) async -> compute(i).
// smem: 2 x (sx[CICH][68] + sw[CICH*3][COT])
template<int CIN, int COUT, int TLEN, int CPAIRS, int CICH>
__device__ __forceinline__ void conv3_body(
    const float* __restrict__ x, const float* __restrict__ wT,
    const float* __restrict__ bias, float* __restrict__ y,
    int b, int t_tile, int co_tile, float* smem)
{
    constexpr int COT = 32 * CPAIRS;
    constexpr int NW4 = CICH * 3 * COT / 4;
    constexpr int BUF = CICH * 68 + CICH * 3 * COT;
    constexpr int NCH = CIN / CICH;

    const int tid = threadIdx.x;
    const int cg = tid & 15, tg = tid >> 4;
    const int tt = tg * 4, ct = cg * 2 * CPAIRS;
    const int t0 = t_tile * 64, co0 = co_tile * COT;
    const bool active = (t0 + tt) < TLEN;

    auto stage = [&](int ch, int buf) {
        float* sx = smem + buf * BUF;
        float* sw = sx + CICH * 68;
        const int ci0 = ch * CICH;
        for (int idx = tid; idx < CICH * 66; idx += 256) {
            int cc = idx / 66, j = idx - cc * 66;
            int t = t0 + j - 1;
            bool p = (t >= 0 && t < TLEN);
            cp_async4(&sx[cc * 68 + j],
                      &x[((size_t)(b * CIN) + ci0 + cc) * TLEN + t], p);
        }
        for (int idx = tid; idx < NW4; idx += 256) {
            int r = idx / (COT / 4), c4 = idx - r * (COT / 4);
            cp_async16(&sw[r * COT + c4 * 4],
                       &wT[(size_t)(ci0 * 3 + r) * COUT + co0 + c4 * 4]);
        }
        CP_COMMIT();
    };

    float2 acc[CPAIRS][4] = {};

    stage(0, 0);
    for (int ch = 0; ch < NCH; ch++) {
        const int buf = ch & 1;
        CP_WAIT0();
        __syncthreads();
        if (ch + 1 < NCH) stage(ch + 1, buf ^ 1);

        if (active) {
            const float* sx = smem + buf * BUF;
            const float* sw = sx + CICH * 68;
            #pragma unroll
            for (int cc = 0; cc < CICH; cc++) {
                const float* xr = &sx[cc * 68 + tt];
                float4 xa = *(const float4*)xr;
                float2 xb = *(const float2*)(xr + 4);
                float2 xv[6] = { dup(xa.x), dup(xa.y), dup(xa.z),
                                 dup(xa.w), dup(xb.x), dup(xb.y) };
                float2 wk[3][CPAIRS];
                #pragma unroll
                for (int k = 0; k < 3; k++) {
                    const float* wb = &sw[(cc * 3 + k) * COT + ct];
                    if constexpr ((CPAIRS & 1) == 0) {
                        #pragma unroll
                        for (int q = 0; q < CPAIRS / 2; q++) {
                            float4 wv = *(const float4*)(wb + 4 * q);
                            wk[k][2*q]   = make_float2(wv.x, wv.y);
                            wk[k][2*q+1] = make_float2(wv.z, wv.w);
                        }
                    } else {
                        #pragma unroll
                        for (int p = 0; p < CPAIRS; p++)
                            wk[k][p] = *(const float2*)(wb + 2 * p);
                    }
                }
                #pragma unroll
                for (int u = 0; u < 4; u++)
                    #pragma unroll
                    for (int p = 0; p < CPAIRS; p++)
                        acc[p][u] = ffma2(wk[0][p], xv[u],
                                    ffma2(wk[1][p], xv[u+1],
                                    ffma2(wk[2][p], xv[u+2], acc[p][u])));
            }
        }
        __syncthreads();
    }

    if (active) {
        #pragma unroll
        for (int p = 0; p < CPAIRS; p++) {
            int co = co0 + ct + 2 * p;
            float2 bv = *(const float2*)&bias[co];
            float4 v0 = { fmaxf(acc[p][0].x + bv.x, 0.f), fmaxf(acc[p][1].x + bv.x, 0.f),
                          fmaxf(acc[p][2].x + bv.x, 0.f), fmaxf(acc[p][3].x + bv.x, 0.f) };
            float4 v1 = { fmaxf(acc[p][0].y + bv.y, 0.f), fmaxf(acc[p][1].y + bv.y, 0.f),
                          fmaxf(acc[p][2].y + bv.y, 0.f), fmaxf(acc[p][3].y + bv.y, 0.f) };
            *(float4*)&y[((size_t)(b * COUT) + co    ) * TLEN + t0 + tt] = v0;
            *(float4*)&y[((size_t)(b * COUT) + co + 1) * TLEN + t0 + tt] = v1;
        }
    }
}

__global__ void __launch_bounds__(256)
stageA_kernel(
    const float* __restrict__ keys, const float* __restrict__ kb1,
    const float* __restrict__ queries, const float* __restrict__ qb1,
    float* __restrict__ k1out, float* __restrict__ q1out)
{
    extern __shared__ float smem[];
    int id = blockIdx.x;
    if (id < 512) {                      // key: CICH=16, buf 7232 fl
        int b = id >> 5, r = id & 31;
        conv3_body<256, 512, 200, 2, 16>(keys, g_kw1T, kb1, k1out,
                                         b, r & 3, r >> 2, smem);
    } else {                             // query: CICH=8, buf 4384 fl
        int j = id - 512;
        conv3_body<80, 160, 800, 5, 8>(queries, g_qw1T, qb1, q1out,
                                       j / 13, j % 13, 0, smem);
    }
}

// =================== STAGE B: key 1x1 + qchain (R11 exact) ================
__device__ __forceinline__ void key1x1_body(
    const float* __restrict__ x, const float* __restrict__ wT,
    const float* __restrict__ bias, float* __restrict__ y,
    int b, int t_tile, float* smem)
{
    float* sx = smem;          // 32*64
    float* sw = smem + 2048;   // 32*80
    const int tid = threadIdx.x;
    const int cg = tid & 7, tg = tid >> 3;
    const int tt = tg * 2, cb = cg * 10;
    const int t0 = t_tile * 64;
    const bool active = (t0 + tt) < 200;
    float2 acc[5][2] = {};

    for (int ci0 = 0; ci0 < 512; ci0 += 32) {
        __syncthreads();
        for (int idx = tid; idx < 2048; idx += 256) {
            int cc = idx >> 6, j = idx & 63;
            int t = t0 + j;
            sx[idx] = (t < 200) ? x[((size_t)(b * 512) + ci0 + cc) * 200 + t] : 0.f;
        }
        for (int idx = tid; idx < 2560; idx += 256)
            sw[idx] = wT[(size_t)ci0 * 80 + idx];
        __syncthreads();
        if (active) {
            #pragma unroll 8
            for (int cc = 0; cc < 32; cc++) {
                float2 xq = *(const float2*)&sx[cc * 64 + tt];
                float2 x0 = dup(xq.x), x1 = dup(xq.y);
                const float2* wp = (const float2*)&sw[cc * 80 + cb];
                #pragma unroll
                for (int p = 0; p < 5; p++) {
                    float2 wd = wp[p];
                    acc[p][0] = ffma2(wd, x0, acc[p][0]);
                    acc[p][1] = ffma2(wd, x1, acc[p][1]);
                }
            }
        }
    }
    if (active) {
        #pragma unroll
        for (int p = 0; p < 5; p++) {
            int co = cb + 2 * p;
            float2 bv = *(const float2*)&bias[co];
            float2 v0 = { acc[p][0].x + bv.x, acc[p][1].x + bv.x };
            float2 v1 = { acc[p][0].y + bv.y, acc[p][1].y + bv.y };
            *(float2*)&y[((size_t)(b * 80) + co    ) * 200 + t0 + tt] = v0;
            *(float2*)&y[((size_t)(b * 80) + co + 1) * 200 + t0 + tt] = v1;
        }
    }
}

__device__ __forceinline__ void qchain_body(
    const float* __restrict__ x, const float* __restrict__ w2T, const float* __restrict__ b2,
    const float* __restrict__ w3T, const float* __restrict__ b3,
    float* __restrict__ y, int b, int t_tile, float* smem)
{
    float* sx  = smem;          // 2048
    float* sw  = smem + 2048;   // 2560
    float* sh2 = smem + 4608;   // 5120
    const int tid = threadIdx.x;
    const int cg = tid & 7, tg = tid >> 3;
    const int tt = tg * 2, cb = cg * 10;
    const int t0 = t_tile * 64;
    const bool active = (t0 + tt) < 800;

    {   // phase 1
        float2 acc[5][2] = {};
        for (int ci0 = 0; ci0 < 160; ci0 += 32) {
            __syncthreads();
            for (int idx = tid; idx < 2048; idx += 256) {
                int cc = idx >> 6, j = idx & 63;
                int t = t0 + j;
                sx[idx] = (t < 800) ? x[((size_t)(b * 160) + ci0 + cc) * 800 + t] : 0.f;
            }
            for (int idx = tid; idx < 2560; idx += 256)
                sw[idx] = w2T[(size_t)ci0 * 80 + idx];
            __syncthreads();
            if (active) {
                #pragma unroll 8
                for (int cc = 0; cc < 32; cc++) {
                    float2 xq = *(const float2*)&sx[cc * 64 + tt];
                    float2 x0 = dup(xq.x), x1 = dup(xq.y);
                    const float2* wp = (const float2*)&sw[cc * 80 + cb];
                    #pragma unroll
                    for (int p = 0; p < 5; p++) {
                        float2 wd = wp[p];
                        acc[p][0] = ffma2(wd, x0, acc[p][0]);
                        acc[p][1] = ffma2(wd, x1, acc[p][1]);
                    }
                }
            }
        }
        if (active) {
            #pragma unroll
            for (int p = 0; p < 5; p++) {
                int co = cb + 2 * p;
                float2 bv = *(const float2*)&b2[co];
                float2 v0 = { fmaxf(acc[p][0].x + bv.x, 0.f), fmaxf(acc[p][1].x + bv.x, 0.f) };
                float2 v1 = { fmaxf(acc[p][0].y + bv.y, 0.f), fmaxf(acc[p][1].y + bv.y, 0.f) };
                *(float2*)&sh2[(co    ) * 64 + tt] = v0;
                *(float2*)&sh2[(co + 1) * 64 + tt] = v1;
            }
        }
    }
    {   // phase 2
        float2 acc[5][2] = {};
        for (int ci0 = 0; ci0 < 80; ci0 += 32) {
            const int CC = (80 - ci0 < 32) ? (80 - ci0) : 32;
            __syncthreads();
            for (int idx = tid; idx < CC * 80; idx += 256)
                sw[idx] = w3T[(size_t)ci0 * 80 + idx];
            __syncthreads();
            if (active) {
                #pragma unroll 8
                for (int cc = 0; cc < CC; cc++) {
                    float2 xq = *(const float2*)&sh2[(ci0 + cc) * 64 + tt];
                    float2 x0 = dup(xq.x), x1 = dup(xq.y);
                    const float2* wp = (const float2*)&sw[cc * 80 + cb];
                    #pragma unroll
                    for (int p = 0; p < 5; p++) {
                        float2 wd = wp[p];
                        acc[p][0] = ffma2(wd, x0, acc[p][0]);
                        acc[p][1] = ffma2(wd, x1, acc[p][1]);
                    }
                }
            }
        }
        if (active) {
            #pragma unroll
            for (int p = 0; p < 5; p++) {
                int co = cb + 2 * p;
                float2 bv = *(const float2*)&b3[co];
                float2 v0 = { acc[p][0].x + bv.x, acc[p][1].x + bv.x };
                float2 v1 = { acc[p][0].y + bv.y, acc[p][1].y + bv.y };
                *(float2*)&y[((size_t)(b * 80) + co    ) * 800 + t0 + tt] = v0;
                *(float2*)&y[((size_t)(b * 80) + co + 1) * 800 + t0 + tt] = v1;
            }
        }
    }
}

__global__ void stageB_kernel(
    const float* __restrict__ k1in, const float* __restrict__ kb2, float* __restrict__ kout,
    const float* __restrict__ q1in, const float* __restrict__ qb2,
    const float* __restrict__ qb3, float* __restrict__ qout)
{
    extern __shared__ float smem[];
    int id = blockIdx.x;
    if (id < 64) key1x1_body(k1in, g_kw2T, kb2, kout, id >> 2, id & 3, smem);
    else {
        int j = id - 64;
        qchain_body(q1in, g_qw2T, qb2, g_qw3T, qb3, qout, j / 13, j % 13, smem);
    }
}

// =================== STAGE C: attention (R8/R9 exact) =====================
__global__ void attention_kernel(const float* __restrict__ q, const float* __restrict__ k,
                                 const float* __restrict__ prior, float* __restrict__ out)
{
    extern __shared__ float smem[];
    float* sq = smem;              // 80*16
    float* sd = smem + 1280;       // 16*200

    const int b    = blockIdx.y;
    const int t1_0 = blockIdx.x * 16;
    const int tid  = threadIdx.x;

    {
        int i = tid;
        if (i < 320) {
            int c = i >> 2, jq = (i & 3) << 2;
            *(float4*)&sq[c * 16 + jq] =
                *(const float4*)&q[((size_t)(b * 80) + c) * 800 + t1_0 + jq];
        }
        i = tid + 256;
        if (i < 320) {
            int c = i >> 2, jq = (i & 3) << 2;
            *(float4*)&sq[c * 16 + jq] =
                *(const float4*)&q[((size_t)(b * 80) + c) * 800 + t1_0 + jq];
        }
    }
    __syncthreads();

    const int sg = tid & 63, jg = tid >> 6;
    if (sg < 50) {
        const int s0 = sg * 4, j0 = jg * 4;
        const float* kp = &k[(size_t)(b * 80) * 200 + s0];
        float2 acc[4][2] = {};
        float2 k2p[2] = {}, q2p[2] = {};

        float4 kbuf[4];
        #pragma unroll
        for (int i = 0; i < 4; i++) kbuf[i] = *(const float4*)(kp + i * 200);

        #pragma unroll
        for (int c0 = 0; c0 < 80; c0 += 4) {
            float4 cur[4];
            #pragma unroll
            for (int i = 0; i < 4; i++) cur[i] = kbuf[i];
            if (c0 + 4 < 80) {
                #pragma unroll
                for (int i = 0; i < 4; i++)
                    kbuf[i] = *(const float4*)(kp + (c0 + 4 + i) * 200);
            }
            #pragma unroll
            for (int i = 0; i < 4; i++) {
                int c = c0 + i;
                float4 kq = cur[i];
                float4 qa = *(const float4*)&sq[c * 16 + j0];
                float2 qp[2] = { {qa.x, qa.y}, {qa.z, qa.w} };
                float2 kpair0 = { kq.x, kq.y }, kpair1 = { kq.z, kq.w };
                k2p[0] = ffma2(kpair0, kpair0, k2p[0]);
                k2p[1] = ffma2(kpair1, kpair1, k2p[1]);
                q2p[0] = ffma2(qp[0], qp[0], q2p[0]);
                q2p[1] = ffma2(qp[1], qp[1], q2p[1]);
                float ks[4] = { kq.x, kq.y, kq.z, kq.w };
                #pragma unroll
                for (int si = 0; si < 4; si++) {
                    float2 kd = dup(ks[si]);
                    acc[si][0] = ffma2(kd, qp[0], acc[si][0]);
                    acc[si][1] = ffma2(kd, qp[1], acc[si][1]);
                }
            }
        }
        float k2s[4] = { k2p[0].x, k2p[0].y, k2p[1].x, k2p[1].y };
        float q2s[4] = { q2p[0].x, q2p[0].y, q2p[1].x, q2p[1].y };
        #pragma unroll
        for (int jj = 0; jj < 4; jj++) {
            int p = jj >> 1;
            float a0 = (jj & 1) ? acc[0][p].y : acc[0][p].x;
            float a1 = (jj & 1) ? acc[1][p].y : acc[1][p].x;
            float a2 = (jj & 1) ? acc[2][p].y : acc[2][p].x;
            float a3 = (jj & 1) ? acc[3][p].y : acc[3][p].x;
            float4 v = { -0.0005f * (q2s[jj] + k2s[0] - 2.f * a0),
                         -0.0005f * (q2s[jj] + k2s[1] - 2.f * a1),
                         -0.0005f * (q2s[jj] + k2s[2] - 2.f * a2),
                         -0.0005f * (q2s[jj] + k2s[3] - 2.f * a3) };
            *(float4*)&sd[(j0 + jj) * 200 + s0] = v;
        }
    }
    __syncthreads();

    const int warp = tid >> 5, lane = tid & 31;
    #pragma unroll
    for (int rr = 0; rr < 2; rr++) {
        int j = warp + rr * 8;
        const float* pr = &prior[((size_t)b * 800 + t1_0 + j) * 200];
        float prv[7];
        #pragma unroll
        for (int i = 0; i < 7; i++) {
            int s = lane + 32 * i;
            prv[i] = (s < 200) ? pr[s] : 1.f;
        }
        float m = -1e30f;
        #pragma unroll
        for (int i = 0; i < 7; i++) {
            int s = lane + 32 * i;
            if (s < 200) m = fmaxf(m, sd[j * 200 + s]);
        }
        #pragma unroll
        for (int o = 16; o; o >>= 1) m = fmaxf(m, __shfl_xor_sync(0xffffffffu, m, o));
        float sum = 0.f;
        #pragma unroll
        for (int i = 0; i < 7; i++) {
            int s = lane + 32 * i;
            if (s < 200) sum += __expf(sd[j * 200 + s] - m);
        }
        #pragma unroll
        for (int o = 16; o; o >>= 1) sum += __shfl_xor_sync(0xffffffffu, sum, o);
        float lse = m + __logf(sum);
        float* op = &out[((size_t)b * 800 + t1_0 + j) * 200];
        #pragma unroll
        for (int i = 0; i < 7; i++) {
            int s = lane + 32 * i;
            if (s < 200) op[s] = sd[j * 200 + s] - lse + __logf(prv[i] + 1e-8f);
        }
    }
}

// -------------------------------- launch ---------------------------------
extern "C" void kernel_launch(void* const* d_in, const int* in_sizes, int n_in,
                              void* d_out, int out_size)
{
    const float* queries = (const float*)d_in[0];
    const float* keys    = (const float*)d_in[1];
    const float* prior   = (const float*)d_in[2];
    const float* kw1 = (const float*)d_in[3];
    const float* kb1 = (const float*)d_in[4];
    const float* kw2 = (const float*)d_in[5];
    const float* kb2 = (const float*)d_in[6];
    const float* qw1 = (const float*)d_in[7];
    const float* qb1 = (const float*)d_in[8];
    const float* qw2 = (const float*)d_in[9];
    const float* qb2 = (const float*)d_in[10];
    const float* qw3 = (const float*)d_in[11];
    const float* qb3 = (const float*)d_in[12];
    float* out = (float*)d_out;

    float *k1buf, *kbuf, *q1buf, *qbuf;
    float *kw1T, *qw1T, *kw2T, *qw2T, *qw3T;
    cudaGetSymbolAddress((void**)&k1buf, g_k1);
    cudaGetSymbolAddress((void**)&kbuf,  g_k);
    cudaGetSymbolAddress((void**)&q1buf, g_q1);
    cudaGetSymbolAddress((void**)&qbuf,  g_qf);
    cudaGetSymbolAddress((void**)&kw1T, g_kw1T);
    cudaGetSymbolAddress((void**)&qw1T, g_qw1T);
    cudaGetSymbolAddress((void**)&kw2T, g_kw2T);
    cudaGetSymbolAddress((void**)&qw2T, g_qw2T);
    cudaGetSymbolAddress((void**)&qw3T, g_qw3T);

    // key buffer: 2*(16*68 + 48*128) = 14464 floats = 57856 B (the max)
    const int smem_A    = 2 * (16 * 68 + 48 * 128) * 4;          // 57856
    const int smem_B    = 9728 * 4;                              // 38912
    const int smem_attn = (1280 + 16 * 200) * 4;                 // 17920

    cudaFuncSetAttribute((const void*)stageA_kernel,
                         cudaFuncAttributeMaxDynamicSharedMemorySize, smem_A);
    cudaFuncSetAttribute((const void*)stageB_kernel,
                         cudaFuncAttributeMaxDynamicSharedMemorySize, smem_B);

    prep_kernel<<<496, 256>>>(kw1, qw1, kw2, qw2, qw3, kw1T, qw1T, kw2T, qw2T, qw3T);
    stageA_kernel<<<720, 256, smem_A>>>(keys, kb1, queries, qb1, k1buf, q1buf);
    stageB_kernel<<<272, 256, smem_B>>>(k1buf, kb2, kbuf, q1buf, qb2, qb3, qbuf);
    attention_kernel<<<dim3(50, 16), 256, smem_attn>>>(qbuf, kbuf, prior, out);
}

// round 14
// speedup vs baseline: 1.3542x; 1.1043x over previous
#include <cuda_runtime.h>
#include <cstdint>
#include <math.h>

// ---------------- scratch (device globals; no allocation) ----------------
__device__ float g_k1  [16 * 512 * 200];   // key conv1 out
__device__ float g_k   [16 *  80 * 200];   // key encoder out
__device__ float g_q1  [16 * 160 * 800];   // query conv1 out
__device__ float g_qf  [16 *  80 * 800];   // query encoder out
__device__ float g_kw1T[768 * 512];        // kw1 transposed [(ci*3+k)][co]
__device__ float g_qw1T[240 * 160];
__device__ float g_kw2T[512 *  80];        // kw2 transposed [ci][co]
__device__ float g_qw2T[160 *  80];
__device__ float g_qw3T[ 80 *  80];

// ---------------- packed fp32x2 FMA (Blackwell) ---------------------------
__device__ __forceinline__ float2 ffma2(float2 a, float2 b, float2 c) {
    unsigned long long ua = *reinterpret_cast<unsigned long long*>(&a);
    unsigned long long ub = *reinterpret_cast<unsigned long long*>(&b);
    unsigned long long uc = *reinterpret_cast<unsigned long long*>(&c);
    unsigned long long ud;
    asm("fma.rn.f32x2 %0, %1, %2, %3;" : "=l"(ud) : "l"(ua), "l"(ub), "l"(uc));
    return *reinterpret_cast<float2*>(&ud);
}
__device__ __forceinline__ float2 dup(float v) { return make_float2(v, v); }

// ---------------- cp.async helpers ----------------------------------------
__device__ __forceinline__ void cp_async4(void* dst, const void* src, bool pred) {
    unsigned int d = (unsigned int)__cvta_generic_to_shared(dst);
    int sz = pred ? 4 : 0;
    asm volatile("cp.async.ca.shared.global [%0], [%1], 4, %2;"
                 :: "r"(d), "l"(src), "r"(sz) : "memory");
}
__device__ __forceinline__ void cp_async16(void* dst, const void* src) {
    unsigned int d = (unsigned int)__cvta_generic_to_shared(dst);
    asm volatile("cp.async.ca.shared.global [%0], [%1], 16;"
                 :: "r"(d), "l"(src) : "memory");
}
#define CP_COMMIT() asm volatile("cp.async.commit_group;" ::: "memory")
#define CP_WAIT0()  asm volatile("cp.async.wait_group 0;" ::: "memory")

// =================== PREP: tiled (coalesced) weight transposes ============
__global__ void prep_kernel(const float* __restrict__ kw1, const float* __restrict__ qw1,
                            const float* __restrict__ kw2, const float* __restrict__ qw2,
                            const float* __restrict__ qw3,
                            float* __restrict__ kw1T, float* __restrict__ qw1T,
                            float* __restrict__ kw2T, float* __restrict__ qw2T,
                            float* __restrict__ qw3T)
{
    __shared__ float tile[32][33];
    int id = blockIdx.x;
    const float* src; float* dst; int R, C, bi, bj;
    if (id < 384)            { src = kw1; dst = kw1T; R = 512; C = 768; bi = id / 24; bj = id % 24; }
    else if ((id -= 384) < 40) { src = qw1; dst = qw1T; R = 160; C = 240; bi = id / 8;  bj = id % 8;  }
    else if ((id -= 40) < 48)  { src = kw2; dst = kw2T; R = 80;  C = 512; bi = id / 16; bj = id % 16; }
    else if ((id -= 48) < 15)  { src = qw2; dst = qw2T; R = 80;  C = 160; bi = id / 5;  bj = id % 5;  }
    else      { id -= 15;        src = qw3; dst = qw3T; R = 80;  C = 80;  bi = id / 3;  bj = id % 3;  }

    const int r0 = bi * 32, c0 = bj * 32;
    const int tx = threadIdx.x & 31, ty = threadIdx.x >> 5;

    #pragma unroll
    for (int yy = ty; yy < 32; yy += 8) {
        int r = r0 + yy, c = c0 + tx;
        tile[yy][tx] = (r < R && c < C) ? src[(size_t)r * C + c] : 0.f;
    }
    __syncthreads();
    #pragma unroll
    for (int yy = ty; yy < 32; yy += 8) {
        int c = c0 + yy, r = r0 + tx;
        if (c < C && r < R) dst[(size_t)c * R + r] = tile[tx][yy];
    }
}

// =================== STAGE A: conv3 with cp.async double buffering ========
template<int CIN, int COUT, int TLEN, int CPAIRS, int CICH>
__device__ __forceinline__ void conv3_body(
    const float* __restrict__ x, const float* __restrict__ wT,
    const float* __restrict__ bias, float* __restrict__ y,
    int b, int t_tile, int co_tile, float* smem)
{
    constexpr int COT = 32 * CPAIRS;
    constexpr int NW4 = CICH * 3 * COT / 4;
    constexpr int BUF = CICH * 68 + CICH * 3 * COT;
    constexpr int NCH = CIN / CICH;

    const int tid = threadIdx.x;
    const int cg = tid & 15, tg = tid >> 4;
    const int tt = tg * 4, ct = cg * 2 * CPAIRS;
    const int t0 = t_tile * 64, co0 = co_tile * COT;
    const bool active = (t0 + tt) < TLEN;

    auto stage = [&](int ch, int buf) {
        float* sx = smem + buf * BUF;
        float* sw = sx + CICH * 68;
        const int ci0 = ch * CICH;
        for (int idx = tid; idx < CICH * 66; idx += 256) {
            int cc = idx / 66, j = idx - cc * 66;
            int t = t0 + j - 1;
            bool p = (t >= 0 && t < TLEN);
            cp_async4(&sx[cc * 68 + j],
                      &x[((size_t)(b * CIN) + ci0 + cc) * TLEN + t], p);
        }
        for (int idx = tid; idx < NW4; idx += 256) {
            int r = idx / (COT / 4), c4 = idx - r * (COT / 4);
            cp_async16(&sw[r * COT + c4 * 4],
                       &wT[(size_t)(ci0 * 3 + r) * COUT + co0 + c4 * 4]);
        }
        CP_COMMIT();
    };

    float2 acc[CPAIRS][4] = {};

    stage(0, 0);
    for (int ch = 0; ch < NCH; ch++) {
        const int buf = ch & 1;
        CP_WAIT0();
        __syncthreads();
        if (ch + 1 < NCH) stage(ch + 1, buf ^ 1);

        if (active) {
            const float* sx = smem + buf * BUF;
            const float* sw = sx + CICH * 68;
            #pragma unroll
            for (int cc = 0; cc < CICH; cc++) {
                const float* xr = &sx[cc * 68 + tt];
                float4 xa = *(const float4*)xr;
                float2 xb = *(const float2*)(xr + 4);
                float2 xv[6] = { dup(xa.x), dup(xa.y), dup(xa.z),
                                 dup(xa.w), dup(xb.x), dup(xb.y) };
                float2 wk[3][CPAIRS];
                #pragma unroll
                for (int k = 0; k < 3; k++) {
                    const float* wb = &sw[(cc * 3 + k) * COT + ct];
                    if constexpr ((CPAIRS & 1) == 0) {
                        #pragma unroll
                        for (int q = 0; q < CPAIRS / 2; q++) {
                            float4 wv = *(const float4*)(wb + 4 * q);
                            wk[k][2*q]   = make_float2(wv.x, wv.y);
                            wk[k][2*q+1] = make_float2(wv.z, wv.w);
                        }
                    } else {
                        #pragma unroll
                        for (int p = 0; p < CPAIRS; p++)
                            wk[k][p] = *(const float2*)(wb + 2 * p);
                    }
                }
                #pragma unroll
                for (int u = 0; u < 4; u++)
                    #pragma unroll
                    for (int p = 0; p < CPAIRS; p++)
                        acc[p][u] = ffma2(wk[0][p], xv[u],
                                    ffma2(wk[1][p], xv[u+1],
                                    ffma2(wk[2][p], xv[u+2], acc[p][u])));
            }
        }
        __syncthreads();
    }

    if (active) {
        #pragma unroll
        for (int p = 0; p < CPAIRS; p++) {
            int co = co0 + ct + 2 * p;
            float2 bv = *(const float2*)&bias[co];
            float4 v0 = { fmaxf(acc[p][0].x + bv.x, 0.f), fmaxf(acc[p][1].x + bv.x, 0.f),
                          fmaxf(acc[p][2].x + bv.x, 0.f), fmaxf(acc[p][3].x + bv.x, 0.f) };
            float4 v1 = { fmaxf(acc[p][0].y + bv.y, 0.f), fmaxf(acc[p][1].y + bv.y, 0.f),
                          fmaxf(acc[p][2].y + bv.y, 0.f), fmaxf(acc[p][3].y + bv.y, 0.f) };
            *(float4*)&y[((size_t)(b * COUT) + co    ) * TLEN + t0 + tt] = v0;
            *(float4*)&y[((size_t)(b * COUT) + co + 1) * TLEN + t0 + tt] = v1;
        }
    }
}

__global__ void __launch_bounds__(256)
stageA_kernel(
    const float* __restrict__ keys, const float* __restrict__ kb1,
    const float* __restrict__ queries, const float* __restrict__ qb1,
    float* __restrict__ k1out, float* __restrict__ q1out)
{
    extern __shared__ float smem[];
    int id = blockIdx.x;
    if (id < 512) {                      // key: CICH=16, CPAIRS=2 -> buf 4160 fl
        int b = id >> 5, r = id & 31;
        conv3_body<256, 512, 200, 2, 16>(keys, g_kw1T, kb1, k1out,
                                         b, r & 3, r >> 2, smem);
    } else {                             // query: CICH=8, CPAIRS=5 -> buf 4384 fl
        int j = id - 512;
        conv3_body<80, 160, 800, 5, 8>(queries, g_qw1T, qb1, q1out,
                                       j / 13, j % 13, 0, smem);
    }
}

// =================== STAGE B: key 1x1 (cp.async piped) + qchain ===========
// key 1x1: t-tile 64, double-buffered staging. 2x(2048+2560) fl = 36864 B.
__device__ __forceinline__ void key1x1_body(
    const float* __restrict__ x, const float* __restrict__ wT,
    const float* __restrict__ bias, float* __restrict__ y,
    int b, int t_tile, float* smem)
{
    constexpr int BUF = 2048 + 2560;
    const int tid = threadIdx.x;
    const int cg = tid & 7, tg = tid >> 3;
    const int tt = tg * 2, cb = cg * 10;
    const int t0 = t_tile * 64;
    const bool active = (t0 + tt) < 200;
    float2 acc[5][2] = {};

    auto stage = [&](int ch, int buf) {
        float* sx = smem + buf * BUF;
        float* sw = sx + 2048;
        const int ci0 = ch * 32;
        for (int idx = tid; idx < 2048; idx += 256) {
            int cc = idx >> 6, j = idx & 63;
            int t = t0 + j;
            cp_async4(&sx[idx], &x[((size_t)(b * 512) + ci0 + cc) * 200 + t],
                      t < 200);
        }
        for (int idx = tid; idx < 640; idx += 256) {
            int r = idx / 20, c4 = idx - r * 20;
            cp_async16(&sw[r * 80 + c4 * 4],
                       &wT[(size_t)(ci0 + r) * 80 + c4 * 4]);
        }
        CP_COMMIT();
    };

    stage(0, 0);
    for (int ch = 0; ch < 16; ch++) {
        const int buf = ch & 1;
        CP_WAIT0();
        __syncthreads();
        if (ch + 1 < 16) stage(ch + 1, buf ^ 1);
        if (active) {
            const float* sx = smem + buf * BUF;
            const float* sw = sx + 2048;
            #pragma unroll 8
            for (int cc = 0; cc < 32; cc++) {
                float2 xq = *(const float2*)&sx[cc * 64 + tt];
                float2 x0 = dup(xq.x), x1 = dup(xq.y);
                const float2* wp = (const float2*)&sw[cc * 80 + cb];
                #pragma unroll
                for (int p = 0; p < 5; p++) {
                    float2 wd = wp[p];
                    acc[p][0] = ffma2(wd, x0, acc[p][0]);
                    acc[p][1] = ffma2(wd, x1, acc[p][1]);
                }
            }
        }
        __syncthreads();
    }
    if (active) {
        #pragma unroll
        for (int p = 0; p < 5; p++) {
            int co = cb + 2 * p;
            float2 bv = *(const float2*)&bias[co];
            float2 v0 = { acc[p][0].x + bv.x, acc[p][1].x + bv.x };
            float2 v1 = { acc[p][0].y + bv.y, acc[p][1].y + bv.y };
            *(float2*)&y[((size_t)(b * 80) + co    ) * 200 + t0 + tt] = v0;
            *(float2*)&y[((size_t)(b * 80) + co + 1) * 200 + t0 + tt] = v1;
        }
    }
}

__device__ __forceinline__ void qchain_body(
    const float* __restrict__ x, const float* __restrict__ w2T, const float* __restrict__ b2,
    const float* __restrict__ w3T, const float* __restrict__ b3,
    float* __restrict__ y, int b, int t_tile, float* smem)
{
    float* sx  = smem;          // 2048
    float* sw  = smem + 2048;   // 2560
    float* sh2 = smem + 4608;   // 5120
    const int tid = threadIdx.x;
    const int cg = tid & 7, tg = tid >> 3;
    const int tt = tg * 2, cb = cg * 10;
    const int t0 = t_tile * 64;
    const bool active = (t0 + tt) < 800;

    {   // phase 1
        float2 acc[5][2] = {};
        for (int ci0 = 0; ci0 < 160; ci0 += 32) {
            __syncthreads();
            for (int idx = tid; idx < 2048; idx += 256) {
                int cc = idx >> 6, j = idx & 63;
                int t = t0 + j;
                sx[idx] = (t < 800) ? x[((size_t)(b * 160) + ci0 + cc) * 800 + t] : 0.f;
            }
            for (int idx = tid; idx < 2560; idx += 256)
                sw[idx] = w2T[(size_t)ci0 * 80 + idx];
            __syncthreads();
            if (active) {
                #pragma unroll 8
                for (int cc = 0; cc < 32; cc++) {
                    float2 xq = *(const float2*)&sx[cc * 64 + tt];
                    float2 x0 = dup(xq.x), x1 = dup(xq.y);
                    const float2* wp = (const float2*)&sw[cc * 80 + cb];
                    #pragma unroll
                    for (int p = 0; p < 5; p++) {
                        float2 wd = wp[p];
                        acc[p][0] = ffma2(wd, x0, acc[p][0]);
                        acc[p][1] = ffma2(wd, x1, acc[p][1]);
                    }
                }
            }
        }
        if (active) {
            #pragma unroll
            for (int p = 0; p < 5; p++) {
                int co = cb + 2 * p;
                float2 bv = *(const float2*)&b2[co];
                float2 v0 = { fmaxf(acc[p][0].x + bv.x, 0.f), fmaxf(acc[p][1].x + bv.x, 0.f) };
                float2 v1 = { fmaxf(acc[p][0].y + bv.y, 0.f), fmaxf(acc[p][1].y + bv.y, 0.f) };
                *(float2*)&sh2[(co    ) * 64 + tt] = v0;
                *(float2*)&sh2[(co + 1) * 64 + tt] = v1;
            }
        }
    }
    {   // phase 2
        float2 acc[5][2] = {};
        for (int ci0 = 0; ci0 < 80; ci0 += 32) {
            const int CC = (80 - ci0 < 32) ? (80 - ci0) : 32;
            __syncthreads();
            for (int idx = tid; idx < CC * 80; idx += 256)
                sw[idx] = w3T[(size_t)ci0 * 80 + idx];
            __syncthreads();
            if (active) {
                #pragma unroll 8
                for (int cc = 0; cc < CC; cc++) {
                    float2 xq = *(const float2*)&sh2[(ci0 + cc) * 64 + tt];
                    float2 x0 = dup(xq.x), x1 = dup(xq.y);
                    const float2* wp = (const float2*)&sw[cc * 80 + cb];
                    #pragma unroll
                    for (int p = 0; p < 5; p++) {
                        float2 wd = wp[p];
                        acc[p][0] = ffma2(wd, x0, acc[p][0]);
                        acc[p][1] = ffma2(wd, x1, acc[p][1]);
                    }
                }
            }
        }
        if (active) {
            #pragma unroll
            for (int p = 0; p < 5; p++) {
                int co = cb + 2 * p;
                float2 bv = *(const float2*)&b3[co];
                float2 v0 = { acc[p][0].x + bv.x, acc[p][1].x + bv.x };
                float2 v1 = { acc[p][0].y + bv.y, acc[p][1].y + bv.y };
                *(float2*)&y[((size_t)(b * 80) + co    ) * 800 + t0 + tt] = v0;
                *(float2*)&y[((size_t)(b * 80) + co + 1) * 800 + t0 + tt] = v1;
            }
        }
    }
}

__global__ void stageB_kernel(
    const float* __restrict__ k1in, const float* __restrict__ kb2, float* __restrict__ kout,
    const float* __restrict__ q1in, const float* __restrict__ qb2,
    const float* __restrict__ qb3, float* __restrict__ qout)
{
    extern __shared__ float smem[];
    int id = blockIdx.x;
    if (id < 64) key1x1_body(k1in, g_kw2T, kb2, kout, id >> 2, id & 3, smem);
    else {
        int j = id - 64;
        qchain_body(q1in, g_qw2T, qb2, g_qw3T, qb3, qout, j / 13, j % 13, smem);
    }
}

// =================== STAGE C: attention (R8 exact) ========================
__global__ void attention_kernel(const float* __restrict__ q, const float* __restrict__ k,
                                 const float* __restrict__ prior, float* __restrict__ out)
{
    extern __shared__ float smem[];
    float* sq = smem;              // 80*16
    float* sd = smem + 1280;       // 16*200

    const int b    = blockIdx.y;
    const int t1_0 = blockIdx.x * 16;
    const int tid  = threadIdx.x;

    {
        int i = tid;
        if (i < 320) {
            int c = i >> 2, jq = (i & 3) << 2;
            *(float4*)&sq[c * 16 + jq] =
                *(const float4*)&q[((size_t)(b * 80) + c) * 800 + t1_0 + jq];
        }
        i = tid + 256;
        if (i < 320) {
            int c = i >> 2, jq = (i & 3) << 2;
            *(float4*)&sq[c * 16 + jq] =
                *(const float4*)&q[((size_t)(b * 80) + c) * 800 + t1_0 + jq];
        }
    }
    __syncthreads();

    const int sg = tid & 63, jg = tid >> 6;
    if (sg < 50) {
        const int s0 = sg * 4, j0 = jg * 4;
        const float* kp = &k[(size_t)(b * 80) * 200 + s0];
        float2 acc[4][2] = {};
        float2 k2p[2] = {}, q2p[2] = {};

        float4 kbuf[4];
        #pragma unroll
        for (int i = 0; i < 4; i++) kbuf[i] = *(const float4*)(kp + i * 200);

        #pragma unroll
        for (int c0 = 0; c0 < 80; c0 += 4) {
            float4 cur[4];
            #pragma unroll
            for (int i = 0; i < 4; i++) cur[i] = kbuf[i];
            if (c0 + 4 < 80) {
                #pragma unroll
                for (int i = 0; i < 4; i++)
                    kbuf[i] = *(const float4*)(kp + (c0 + 4 + i) * 200);
            }
            #pragma unroll
            for (int i = 0; i < 4; i++) {
                int c = c0 + i;
                float4 kq = cur[i];
                float4 qa = *(const float4*)&sq[c * 16 + j0];
                float2 qp[2] = { {qa.x, qa.y}, {qa.z, qa.w} };
                float2 kpair0 = { kq.x, kq.y }, kpair1 = { kq.z, kq.w };
                k2p[0] = ffma2(kpair0, kpair0, k2p[0]);
                k2p[1] = ffma2(kpair1, kpair1, k2p[1]);
                q2p[0] = ffma2(qp[0], qp[0], q2p[0]);
                q2p[1] = ffma2(qp[1], qp[1], q2p[1]);
                float ks[4] = { kq.x, kq.y, kq.z, kq.w };
                #pragma unroll
                for (int si = 0; si < 4; si++) {
                    float2 kd = dup(ks[si]);
                    acc[si][0] = ffma2(kd, qp[0], acc[si][0]);
                    acc[si][1] = ffma2(kd, qp[1], acc[si][1]);
                }
            }
        }
        float k2s[4] = { k2p[0].x, k2p[0].y, k2p[1].x, k2p[1].y };
        float q2s[4] = { q2p[0].x, q2p[0].y, q2p[1].x, q2p[1].y };
        #pragma unroll
        for (int jj = 0; jj < 4; jj++) {
            int p = jj >> 1;
            float a0 = (jj & 1) ? acc[0][p].y : acc[0][p].x;
            float a1 = (jj & 1) ? acc[1][p].y : acc[1][p].x;
            float a2 = (jj & 1) ? acc[2][p].y : acc[2][p].x;
            float a3 = (jj & 1) ? acc[3][p].y : acc[3][p].x;
            float4 v = { -0.0005f * (q2s[jj] + k2s[0] - 2.f * a0),
                         -0.0005f * (q2s[jj] + k2s[1] - 2.f * a1),
                         -0.0005f * (q2s[jj] + k2s[2] - 2.f * a2),
                         -0.0005f * (q2s[jj] + k2s[3] - 2.f * a3) };
            *(float4*)&sd[(j0 + jj) * 200 + s0] = v;
        }
    }
    __syncthreads();

    const int warp = tid >> 5, lane = tid & 31;
    #pragma unroll
    for (int rr = 0; rr < 2; rr++) {
        int j = warp + rr * 8;
        const float* pr = &prior[((size_t)b * 800 + t1_0 + j) * 200];
        float prv[7];
        #pragma unroll
        for (int i = 0; i < 7; i++) {
            int s = lane + 32 * i;
            prv[i] = (s < 200) ? pr[s] : 1.f;
        }
        float m = -1e30f;
        #pragma unroll
        for (int i = 0; i < 7; i++) {
            int s = lane + 32 * i;
            if (s < 200) m = fmaxf(m, sd[j * 200 + s]);
        }
        #pragma unroll
        for (int o = 16; o; o >>= 1) m = fmaxf(m, __shfl_xor_sync(0xffffffffu, m, o));
        float sum = 0.f;
        #pragma unroll
        for (int i = 0; i < 7; i++) {
            int s = lane + 32 * i;
            if (s < 200) sum += __expf(sd[j * 200 + s] - m);
        }
        #pragma unroll
        for (int o = 16; o; o >>= 1) sum += __shfl_xor_sync(0xffffffffu, sum, o);
        float lse = m + __logf(sum);
        float* op = &out[((size_t)b * 800 + t1_0 + j) * 200];
        #pragma unroll
        for (int i = 0; i < 7; i++) {
            int s = lane + 32 * i;
            if (s < 200) op[s] = sd[j * 200 + s] - lse + __logf(prv[i] + 1e-8f);
        }
    }
}

// -------------------------------- launch ---------------------------------
extern "C" void kernel_launch(void* const* d_in, const int* in_sizes, int n_in,
                              void* d_out, int out_size)
{
    const float* queries = (const float*)d_in[0];
    const float* keys    = (const float*)d_in[1];
    const float* prior   = (const float*)d_in[2];
    const float* kw1 = (const float*)d_in[3];
    const float* kb1 = (const float*)d_in[4];
    const float* kw2 = (const float*)d_in[5];
    const float* kb2 = (const float*)d_in[6];
    const float* qw1 = (const float*)d_in[7];
    const float* qb1 = (const float*)d_in[8];
    const float* qw2 = (const float*)d_in[9];
    const float* qb2 = (const float*)d_in[10];
    const float* qw3 = (const float*)d_in[11];
    const float* qb3 = (const float*)d_in[12];
    float* out = (float*)d_out;

    float *k1buf, *kbuf, *q1buf, *qbuf;
    float *kw1T, *qw1T, *kw2T, *qw2T, *qw3T;
    cudaGetSymbolAddress((void**)&k1buf, g_k1);
    cudaGetSymbolAddress((void**)&kbuf,  g_k);
    cudaGetSymbolAddress((void**)&q1buf, g_q1);
    cudaGetSymbolAddress((void**)&qbuf,  g_qf);
    cudaGetSymbolAddress((void**)&kw1T, g_kw1T);
    cudaGetSymbolAddress((void**)&qw1T, g_qw1T);
    cudaGetSymbolAddress((void**)&kw2T, g_kw2T);
    cudaGetSymbolAddress((void**)&qw2T, g_qw2T);
    cudaGetSymbolAddress((void**)&qw3T, g_qw3T);

    // exact smem: key buf 2*4160=8320 fl (33280 B), query buf 2*4384=8768 fl (35072 B)
    const int smem_A    = 2 * (8 * 68 + 24 * 160) * 4;           // 35072
    const int smem_B    = 9728 * 4;                              // 38912 (qchain max)
    const int smem_attn = (1280 + 16 * 200) * 4;                 // 17920

    cudaFuncSetAttribute((const void*)stageA_kernel,
                         cudaFuncAttributeMaxDynamicSharedMemorySize, smem_A);
    cudaFuncSetAttribute((const void*)stageB_kernel,
                         cudaFuncAttributeMaxDynamicSharedMemorySize, smem_B);

    prep_kernel<<<496, 256>>>(kw1, qw1, kw2, qw2, qw3, kw1T, qw1T, kw2T, qw2T, qw3T);
    stageA_kernel<<<720, 256, smem_A>>>(keys, kb1, queries, qb1, k1buf, q1buf);
    stageB_kernel<<<272, 256, smem_B>>>(k1buf, kb2, kbuf, q1buf, qb2, qb3, qbuf);
    attention_kernel<<<dim3(50, 16), 256, smem_attn>>>(qbuf, kbuf, prior, out);
}